// round 14
// baseline (speedup 1.0000x reference)
#include <cuda_runtime.h>
#include <cuda_bf16.h>
#include <math.h>
#include <float.h>

#define NN 50000
#define EE 800000

// ---------------- persistent scratch (device globals; no allocation) ----------------
__device__ __nv_bfloat16 g_ftb[NN * 160];   // transformed features [N, H*F], bf16
__device__ float g_rst[NN * 160];   // layer output (post message-passing)
__device__ float g_sk [NN * 160];   // skip + bias buffer
__device__ float g_el [NN * 4];
__device__ float g_er [NN * 4];
__device__ float g_ex [EE * 4];     // staging for rare high-degree nodes
__device__ int   g_rowptr[NN + 1];
__device__ int   g_tmp   [NN];
__device__ int   g_csr_src[EE];
__device__ float g_bnsum[2][128], g_bnsq[2][128];   // ping-pong BN stats

__device__ __forceinline__ float lrelu(float x) { return x > 0.f ? x : 0.2f * x; }

__device__ __forceinline__ float tf32r(float x) {
    unsigned u;
    asm("cvt.rna.tf32.f32 %0, %1;" : "=r"(u) : "f"(x));
    return __uint_as_float(u);
}

__device__ __forceinline__ void mma_tf32(float* c, const unsigned* a, const unsigned* b) {
    asm volatile(
        "mma.sync.aligned.m16n8k8.row.col.f32.tf32.tf32.f32 "
        "{%0,%1,%2,%3}, {%4,%5,%6,%7}, {%8,%9}, {%0,%1,%2,%3};\n"
        : "+f"(c[0]), "+f"(c[1]), "+f"(c[2]), "+f"(c[3])
        : "r"(a[0]), "r"(a[1]), "r"(a[2]), "r"(a[3]), "r"(b[0]), "r"(b[1]));
}

// load 4 consecutive bf16 (8 bytes) and widen to float4
__device__ __forceinline__ float4 ld_bf16x4(const __nv_bfloat16* p) {
    __nv_bfloat162 pr[2];
    *(uint2*)pr = *(const uint2*)p;
    float2 a = __bfloat1622float2(pr[0]);
    float2 b = __bfloat1622float2(pr[1]);
    return make_float4(a.x, a.y, b.x, b.y);
}

// ================= CSR build =================
__global__ void zero_all_kernel()
{
    int i = blockIdx.x * blockDim.x + threadIdx.x;
    if (i < NN)  g_tmp[i] = 0;
    if (i < 128) {
        g_bnsum[0][i] = 0.f; g_bnsq[0][i] = 0.f;
        g_bnsum[1][i] = 0.f; g_bnsq[1][i] = 0.f;
    }
}

__global__ void hist_kernel(const int* __restrict__ dst)
{
    int e = blockIdx.x * blockDim.x + threadIdx.x;
    if (e < EE) atomicAdd(&g_tmp[dst[e]], 1);
}

// one-block scan of all NN counts in dynamic smem -> g_rowptr & g_tmp
extern __shared__ int s_scan[];
__global__ __launch_bounds__(1024) void scan_all_kernel()
{
    __shared__ int wsum[32];
    const int t = threadIdx.x, lane = t & 31, wid = t >> 5;
    for (int i = t; i < NN; i += 1024) s_scan[i] = g_tmp[i];
    __syncthreads();

    const int C = (NN + 1023) / 1024;      // 49
    const int base = t * C;
    int sum = 0;
#pragma unroll 7
    for (int i = 0; i < C; i++) {
        int idx = base + i;
        if (idx < NN) sum += s_scan[idx];
    }
    int x = sum;
#pragma unroll
    for (int o = 1; o < 32; o <<= 1) {
        int y = __shfl_up_sync(0xffffffffu, x, o);
        if (lane >= o) x += y;
    }
    if (lane == 31) wsum[wid] = x;
    __syncthreads();
    if (wid == 0) {
        int w = wsum[lane];
#pragma unroll
        for (int o = 1; o < 32; o <<= 1) {
            int y = __shfl_up_sync(0xffffffffu, w, o);
            if (lane >= o) w += y;
        }
        wsum[lane] = w;
    }
    __syncthreads();
    int run = (x - sum) + (wid ? wsum[wid - 1] : 0);
#pragma unroll 7
    for (int i = 0; i < C; i++) {
        int idx = base + i;
        if (idx < NN) { int v = s_scan[idx]; s_scan[idx] = run; run += v; }
    }
    __syncthreads();
    for (int i = t; i < NN; i += 1024) {
        int v = s_scan[i];
        g_rowptr[i] = v;
        g_tmp[i]    = v;
    }
    if (t == 0) g_rowptr[NN] = EE;
}

__global__ void scatter_kernel(const int* __restrict__ src, const int* __restrict__ dst)
{
    int e = blockIdx.x * blockDim.x + threadIdx.x;
    if (e >= EE) return;
    int pos = atomicAdd(&g_tmp[dst[e]], 1);
    g_csr_src[pos] = src[e];
}

// ---------------- merged tf32 GEMM: warps 0-3 -> fc, warps 4-7 -> lin, shared A ----
// Block tile: 256 rows x 32 cols per matrix; each warp owns 64 rows (4x4 mma tiles).
// fc output -> bf16 g_ftb (+ optional fused el/er for OD=128); lin -> fp32 sk (+bias)
// BN: x <- relu(a*x+b) on A-tile load; scale/shift computed in-block from raw stats.
template<int OD, bool BN>
__global__ __launch_bounds__(256)
void gemm_tc(const float* __restrict__ X,
             const float* __restrict__ Wfc, const float* __restrict__ Wlin,
             const float* __restrict__ bias, __nv_bfloat16* __restrict__ ft_out,
             float* __restrict__ sk_out,
             const float* __restrict__ al, const float* __restrict__ ar,
             const float* __restrict__ gam, const float* __restrict__ be, int sel)
{
    __shared__ float As[256 * 37];        // [m][k]  (37.9 KB)
    __shared__ float Bs[2 * 32 * 37];     // [mat][n][k]
    __shared__ float s_a[128], s_b[128];
    const int tid  = threadIdx.x;
    const int warp = tid >> 5, lane = tid & 31;
    const int g    = lane >> 2, t = lane & 3;
    const bool isFC = warp < 4;
    const int wr   = warp & 3;            // 64-row group within matrix
    const int row0 = blockIdx.x * 256;
    const int cb   = blockIdx.y;
    const int col0 = cb * 32;

    if (BN) {
        if (tid < 128) {
            float sum = g_bnsum[sel][tid], sq = g_bnsq[sel][tid];
            const float invN = 1.f / (float)NN;
            float mean = sum * invN;
            float var  = sq * invN - mean * mean;
            float a = __ldg(gam + tid) * rsqrtf(var + 1e-5f);
            s_a[tid] = a;
            s_b[tid] = __ldg(be + tid) - mean * a;
        }
        __syncthreads();
    }

    float c[4][4][4];
#pragma unroll
    for (int i = 0; i < 4; i++)
#pragma unroll
        for (int j = 0; j < 4; j++)
#pragma unroll
            for (int q = 0; q < 4; q++) c[i][j][q] = 0.f;

#pragma unroll
    for (int kb = 0; kb < 128; kb += 32) {
        // A tile: 256 rows x 32 k (2048 float4 slots / 256 threads = 8 iters)
#pragma unroll
        for (int j = 0; j < 8; j++) {
            int i4 = tid + j * 256;
            int r  = i4 >> 3;
            int k4 = (i4 & 7) << 2;
            float4 v = make_float4(0.f, 0.f, 0.f, 0.f);
            if (row0 + r < NN)
                v = *(const float4*)(X + (size_t)(row0 + r) * 128 + kb + k4);
            if (BN) {
                v.x = fmaxf(s_a[kb + k4 + 0] * v.x + s_b[kb + k4 + 0], 0.f);
                v.y = fmaxf(s_a[kb + k4 + 1] * v.y + s_b[kb + k4 + 1], 0.f);
                v.z = fmaxf(s_a[kb + k4 + 2] * v.z + s_b[kb + k4 + 2], 0.f);
                v.w = fmaxf(s_a[kb + k4 + 3] * v.w + s_b[kb + k4 + 3], 0.f);
            }
            float* ap = &As[r * 37 + k4];
            ap[0] = tf32r(v.x); ap[1] = tf32r(v.y); ap[2] = tf32r(v.z); ap[3] = tf32r(v.w);
        }
        // B tiles: both matrices, 512 float4 slots / 256 threads = 2 iters
#pragma unroll
        for (int j = 0; j < 2; j++) {
            int i4 = tid + j * 256;
            int m  = i4 >> 8;
            int rr = i4 & 255;
            int k  = rr >> 3;
            int n4 = (rr & 7) << 2;
            const float* Wm = m ? Wlin : Wfc;
            float4 v = *(const float4*)(Wm + (size_t)(kb + k) * OD + col0 + n4);
            float* bp = Bs + m * (32 * 37);
            bp[(n4 + 0) * 37 + k] = tf32r(v.x);
            bp[(n4 + 1) * 37 + k] = tf32r(v.y);
            bp[(n4 + 2) * 37 + k] = tf32r(v.z);
            bp[(n4 + 3) * 37 + k] = tf32r(v.w);
        }
        __syncthreads();
        const float* Bsel = Bs + (isFC ? 0 : 1) * (32 * 37);
#pragma unroll
        for (int ks = 0; ks < 4; ks++) {
            const int k0 = ks * 8;
            unsigned a[4][4], b[4][2];
            const int mbase = wr * 64;
#pragma unroll
            for (int i = 0; i < 4; i++) {
                const float* ap = As + (mbase + i * 16 + g) * 37 + k0 + t;
                a[i][0] = __float_as_uint(ap[0]);
                a[i][1] = __float_as_uint(ap[8 * 37]);
                a[i][2] = __float_as_uint(ap[4]);
                a[i][3] = __float_as_uint(ap[8 * 37 + 4]);
            }
#pragma unroll
            for (int j = 0; j < 4; j++) {
                const float* bp = Bsel + (j * 8 + g) * 37 + k0 + t;
                b[j][0] = __float_as_uint(bp[0]);
                b[j][1] = __float_as_uint(bp[4]);
            }
#pragma unroll
            for (int i = 0; i < 4; i++)
#pragma unroll
                for (int j = 0; j < 4; j++)
                    mma_tf32(c[i][j], a[i], b[j]);
        }
        __syncthreads();
    }

#pragma unroll
    for (int i = 0; i < 4; i++) {
        int r = row0 + wr * 64 + i * 16 + g;
#pragma unroll
        for (int j = 0; j < 4; j++) {
            int cc = col0 + j * 8 + 2 * t;
            if (isFC) {
                if (r < NN) {
                    __nv_bfloat162 o = __float22bfloat162_rn(
                        make_float2(c[i][j][0], c[i][j][1]));
                    *(__nv_bfloat162*)(ft_out + (size_t)r * OD + cc) = o;
                }
                if (r + 8 < NN) {
                    __nv_bfloat162 o = __float22bfloat162_rn(
                        make_float2(c[i][j][2], c[i][j][3]));
                    *(__nv_bfloat162*)(ft_out + (size_t)(r + 8) * OD + cc) = o;
                }
            } else {
                float bx = __ldg(bias + cc), by = __ldg(bias + cc + 1);
                if (r < NN) {
                    float2 o = make_float2(c[i][j][0] + bx, c[i][j][1] + by);
                    *(float2*)(sk_out + (size_t)r * OD + cc) = o;
                }
                if (r + 8 < NN) {
                    float2 o = make_float2(c[i][j][2] + bx, c[i][j][3] + by);
                    *(float2*)(sk_out + (size_t)(r + 8) * OD + cc) = o;
                }
            }
        }
    }

    if (OD == 128 && isFC && al != nullptr) {   // fused el/er: col block cb == head
        const int h = cb;
#pragma unroll
        for (int i = 0; i < 4; i++) {
            float el0 = 0.f, el8 = 0.f, er0 = 0.f, er8 = 0.f;
#pragma unroll
            for (int j = 0; j < 4; j++) {
                int lc = j * 8 + 2 * t;
                float a0 = __ldg(al + h * 32 + lc), a1 = __ldg(al + h * 32 + lc + 1);
                float r0 = __ldg(ar + h * 32 + lc), r1 = __ldg(ar + h * 32 + lc + 1);
                el0 += c[i][j][0] * a0 + c[i][j][1] * a1;
                el8 += c[i][j][2] * a0 + c[i][j][3] * a1;
                er0 += c[i][j][0] * r0 + c[i][j][1] * r1;
                er8 += c[i][j][2] * r0 + c[i][j][3] * r1;
            }
#pragma unroll
            for (int o = 1; o <= 2; o <<= 1) {
                el0 += __shfl_xor_sync(0xffffffffu, el0, o);
                el8 += __shfl_xor_sync(0xffffffffu, el8, o);
                er0 += __shfl_xor_sync(0xffffffffu, er0, o);
                er8 += __shfl_xor_sync(0xffffffffu, er8, o);
            }
            if (t == 0) {
                int r = row0 + wr * 64 + i * 16 + g;
                if (r < NN)     { g_el[r * 4 + h] = el0;       g_er[r * 4 + h] = er0; }
                if (r + 8 < NN) { g_el[(r + 8) * 4 + h] = el8; g_er[(r + 8) * 4 + h] = er8; }
            }
        }
    }
}

// ---------------- el/er for layer 2 (F=40, heads not block-aligned) ----------------
__global__ void elr40_kernel(const float* __restrict__ al, const float* __restrict__ ar)
{
    int i = blockIdx.x * blockDim.x + threadIdx.x;
    if (i >= NN * 4) return;
    int h = i & 3;
    const __nv_bfloat16* f = g_ftb + (size_t)(i >> 2) * 160 + h * 40;
    float a = 0.f, b = 0.f;
#pragma unroll
    for (int j = 0; j < 10; j++) {
        float4 v = ld_bf16x4(f + j * 4);
        float a0 = __ldg(al + h * 40 + j * 4 + 0), a1 = __ldg(al + h * 40 + j * 4 + 1);
        float a2 = __ldg(al + h * 40 + j * 4 + 2), a3 = __ldg(al + h * 40 + j * 4 + 3);
        float b0 = __ldg(ar + h * 40 + j * 4 + 0), b1 = __ldg(ar + h * 40 + j * 4 + 1);
        float b2 = __ldg(ar + h * 40 + j * 4 + 2), b3 = __ldg(ar + h * 40 + j * 4 + 3);
        a += v.x * a0 + v.y * a1 + v.z * a2 + v.w * a3;
        b += v.x * b0 + v.y * b1 + v.z * b2 + v.w * b3;
    }
    g_el[i] = a;
    g_er[i] = b;
}

// ================= fused per-dst softmax + aggregation (warp per node) =========
// MODE 0: rst = sk + msg, accumulate BN stats into buffer [sel].
// MODE 1: head-mean + log_softmax -> out.
template<int OD, int F, int MODE>
__global__ __launch_bounds__(256)
void gat_node_kernel(const float* __restrict__ bias_last, float* __restrict__ out, int sel)
{
    constexpr int NR = (OD / 4 + 31) / 32;
    __shared__ float s_sum[128], s_sq[128];
    __shared__ float s_row[8][160];
    __shared__ int   s_sn [8][32];
    __shared__ float s_att[8][32][4];

    const int tid = threadIdx.x;
    if (MODE == 0) {
        if (tid < 128) { s_sum[tid] = 0.f; s_sq[tid] = 0.f; }
        __syncthreads();
    }
    const int wn   = (blockIdx.x * 256 + tid) >> 5;
    const int lane = tid & 31;
    const int warp = tid >> 5;
    const bool active = wn < NN;

    float4 acc[NR];
    int headr[NR];
#pragma unroll
    for (int rp = 0; rp < NR; rp++) {
        acc[rp] = make_float4(0.f, 0.f, 0.f, 0.f);
        headr[rp] = ((lane + rp * 32) * 4) / F;
    }

    if (active) {
        const int beg = g_rowptr[wn], end = g_rowptr[wn + 1];
        const int deg = end - beg;
        const float4 er = *(const float4*)(g_er + (size_t)wn * 4);

        if (deg <= 32) {
            // ---- one gather pass, lane-local edge ----
            int sn = -1;
            float4 ev = make_float4(-FLT_MAX, -FLT_MAX, -FLT_MAX, -FLT_MAX);
            if (lane < deg) {
                sn = g_csr_src[beg + lane];
                float4 l = *(const float4*)(g_el + (size_t)sn * 4);
                ev.x = lrelu(l.x + er.x);
                ev.y = lrelu(l.y + er.y);
                ev.z = lrelu(l.z + er.z);
                ev.w = lrelu(l.w + er.w);
            }
            float4 m = ev;
#pragma unroll
            for (int o = 16; o; o >>= 1) {
                m.x = fmaxf(m.x, __shfl_xor_sync(0xffffffffu, m.x, o));
                m.y = fmaxf(m.y, __shfl_xor_sync(0xffffffffu, m.y, o));
                m.z = fmaxf(m.z, __shfl_xor_sync(0xffffffffu, m.z, o));
                m.w = fmaxf(m.w, __shfl_xor_sync(0xffffffffu, m.w, o));
            }
            float4 ex = make_float4(0.f, 0.f, 0.f, 0.f);
            if (lane < deg) {
                ex.x = __expf(ev.x - m.x);
                ex.y = __expf(ev.y - m.y);
                ex.z = __expf(ev.z - m.z);
                ex.w = __expf(ev.w - m.w);
            }
            float4 s = ex;
#pragma unroll
            for (int o = 16; o; o >>= 1) {
                s.x += __shfl_xor_sync(0xffffffffu, s.x, o);
                s.y += __shfl_xor_sync(0xffffffffu, s.y, o);
                s.z += __shfl_xor_sync(0xffffffffu, s.z, o);
                s.w += __shfl_xor_sync(0xffffffffu, s.w, o);
            }
            s_sn[warp][lane] = sn;
            s_att[warp][lane][0] = ex.x / s.x;
            s_att[warp][lane][1] = ex.y / s.y;
            s_att[warp][lane][2] = ex.z / s.z;
            s_att[warp][lane][3] = ex.w / s.w;
            __syncwarp();

#pragma unroll 4
            for (int i = 0; i < deg; i++) {
                int si = s_sn[warp][i];
                const __nv_bfloat16* fp = g_ftb + (size_t)si * OD;
#pragma unroll
                for (int rp = 0; rp < NR; rp++) {
                    int j4 = lane + rp * 32;
                    if (j4 < OD / 4) {
                        float a = s_att[warp][i][headr[rp]];
                        float4 f = ld_bf16x4(fp + j4 * 4);
                        acc[rp].x += a * f.x;
                        acc[rp].y += a * f.y;
                        acc[rp].z += a * f.z;
                        acc[rp].w += a * f.w;
                    }
                }
            }
        } else {
            // ---- rare high-degree fallback: 3-phase with staging ----
            float4 m = make_float4(-FLT_MAX, -FLT_MAX, -FLT_MAX, -FLT_MAX);
            for (int i = beg + lane; i < end; i += 32) {
                int sn = g_csr_src[i];
                float4 l = *(const float4*)(g_el + (size_t)sn * 4);
                m.x = fmaxf(m.x, lrelu(l.x + er.x));
                m.y = fmaxf(m.y, lrelu(l.y + er.y));
                m.z = fmaxf(m.z, lrelu(l.z + er.z));
                m.w = fmaxf(m.w, lrelu(l.w + er.w));
            }
#pragma unroll
            for (int o = 16; o; o >>= 1) {
                m.x = fmaxf(m.x, __shfl_xor_sync(0xffffffffu, m.x, o));
                m.y = fmaxf(m.y, __shfl_xor_sync(0xffffffffu, m.y, o));
                m.z = fmaxf(m.z, __shfl_xor_sync(0xffffffffu, m.z, o));
                m.w = fmaxf(m.w, __shfl_xor_sync(0xffffffffu, m.w, o));
            }
            float4 s = make_float4(0.f, 0.f, 0.f, 0.f);
            for (int i = beg + lane; i < end; i += 32) {
                int sn = g_csr_src[i];
                float4 l = *(const float4*)(g_el + (size_t)sn * 4);
                float4 ex;
                ex.x = __expf(lrelu(l.x + er.x) - m.x);
                ex.y = __expf(lrelu(l.y + er.y) - m.y);
                ex.z = __expf(lrelu(l.z + er.z) - m.z);
                ex.w = __expf(lrelu(l.w + er.w) - m.w);
                *(float4*)(g_ex + (size_t)i * 4) = ex;
                s.x += ex.x; s.y += ex.y; s.z += ex.z; s.w += ex.w;
            }
#pragma unroll
            for (int o = 16; o; o >>= 1) {
                s.x += __shfl_xor_sync(0xffffffffu, s.x, o);
                s.y += __shfl_xor_sync(0xffffffffu, s.y, o);
                s.z += __shfl_xor_sync(0xffffffffu, s.z, o);
                s.w += __shfl_xor_sync(0xffffffffu, s.w, o);
            }
            float4 inv = make_float4(1.f / s.x, 1.f / s.y, 1.f / s.z, 1.f / s.w);
            float invh[NR];
#pragma unroll
            for (int rp = 0; rp < NR; rp++) {
                int hh = headr[rp];
                invh[rp] = (hh == 0) ? inv.x : (hh == 1) ? inv.y : (hh == 2) ? inv.z : inv.w;
            }
#pragma unroll 4
            for (int i = beg; i < end; i++) {
                int sn = g_csr_src[i];
                float4 exv = *(const float4*)(g_ex + (size_t)i * 4);
                const __nv_bfloat16* fp = g_ftb + (size_t)sn * OD;
#pragma unroll
                for (int rp = 0; rp < NR; rp++) {
                    int j4 = lane + rp * 32;
                    if (j4 < OD / 4) {
                        int hh = headr[rp];
                        float a = ((hh == 0) ? exv.x : (hh == 1) ? exv.y :
                                   (hh == 2) ? exv.z : exv.w) * invh[rp];
                        float4 f = ld_bf16x4(fp + j4 * 4);
                        acc[rp].x += a * f.x;
                        acc[rp].y += a * f.y;
                        acc[rp].z += a * f.z;
                        acc[rp].w += a * f.w;
                    }
                }
            }
        }
    }

    if (MODE == 0) {
        if (active) {
            const float* skp = g_sk  + (size_t)wn * OD;
            float*       rp_ = g_rst + (size_t)wn * OD;
#pragma unroll
            for (int rp = 0; rp < NR; rp++) {
                int j4 = lane + rp * 32;
                if (j4 < OD / 4) {
                    float4 sk = *(const float4*)(skp + j4 * 4);
                    float4 r;
                    r.x = sk.x + acc[rp].x; r.y = sk.y + acc[rp].y;
                    r.z = sk.z + acc[rp].z; r.w = sk.w + acc[rp].w;
                    *(float4*)(rp_ + j4 * 4) = r;
                    int c0 = j4 * 4;
                    atomicAdd(&s_sum[c0 + 0], r.x); atomicAdd(&s_sq[c0 + 0], r.x * r.x);
                    atomicAdd(&s_sum[c0 + 1], r.y); atomicAdd(&s_sq[c0 + 1], r.y * r.y);
                    atomicAdd(&s_sum[c0 + 2], r.z); atomicAdd(&s_sq[c0 + 2], r.z * r.z);
                    atomicAdd(&s_sum[c0 + 3], r.w); atomicAdd(&s_sq[c0 + 3], r.w * r.w);
                }
            }
        }
        __syncthreads();
        if (tid < 128) {
            atomicAdd(&g_bnsum[sel][tid], s_sum[tid]);
            atomicAdd(&g_bnsq[sel][tid],  s_sq[tid]);
        }
    } else {
        if (active) {
            const float* skp = g_sk + (size_t)wn * OD;
#pragma unroll
            for (int rp = 0; rp < NR; rp++) {
                int j4 = lane + rp * 32;
                if (j4 < OD / 4) {
                    float4 sk = *(const float4*)(skp + j4 * 4);
                    float* d = &s_row[warp][j4 * 4];
                    d[0] = sk.x + acc[rp].x;
                    d[1] = sk.y + acc[rp].y;
                    d[2] = sk.z + acc[rp].z;
                    d[3] = sk.w + acc[rp].w;
                }
            }
            __syncwarp();
            const float* r = s_row[warp];
            float v0 = 0.25f * (r[lane] + r[40 + lane] + r[80 + lane] + r[120 + lane])
                     + __ldg(bias_last + lane);
            float v1 = -FLT_MAX;
            if (lane < 8) {
                int c1 = lane + 32;
                v1 = 0.25f * (r[c1] + r[40 + c1] + r[80 + c1] + r[120 + c1])
                   + __ldg(bias_last + c1);
            }
            float mx = fmaxf(v0, v1);
#pragma unroll
            for (int o = 16; o; o >>= 1) mx = fmaxf(mx, __shfl_xor_sync(0xffffffffu, mx, o));
            float se = __expf(v0 - mx) + (lane < 8 ? __expf(v1 - mx) : 0.f);
#pragma unroll
            for (int o = 16; o; o >>= 1) se += __shfl_xor_sync(0xffffffffu, se, o);
            float lse = logf(se);
            out[(size_t)wn * 40 + lane] = v0 - mx - lse;
            if (lane < 8) out[(size_t)wn * 40 + lane + 32] = v1 - mx - lse;
        }
    }
}

// ---------------- launch ----------------
extern "C" void kernel_launch(void* const* d_in, const int* in_sizes, int n_in,
                              void* d_out, int out_size)
{
    (void)in_sizes; (void)n_in; (void)out_size;
    const float* feat   = (const float*)d_in[0];
    const int*   src    = (const int*)  d_in[1];
    const int*   dst    = (const int*)  d_in[2];
    const float* w_fc0  = (const float*)d_in[3];
    const float* al0    = (const float*)d_in[4];
    const float* ar0    = (const float*)d_in[5];
    const float* b0     = (const float*)d_in[6];
    const float* w_lin0 = (const float*)d_in[7];
    const float* gam0   = (const float*)d_in[8];
    const float* be0    = (const float*)d_in[9];
    const float* w_fc1  = (const float*)d_in[10];
    const float* al1    = (const float*)d_in[11];
    const float* ar1    = (const float*)d_in[12];
    const float* b1     = (const float*)d_in[13];
    const float* w_lin1 = (const float*)d_in[14];
    const float* gam1   = (const float*)d_in[15];
    const float* be1    = (const float*)d_in[16];
    const float* w_fc2  = (const float*)d_in[17];
    const float* al2    = (const float*)d_in[18];
    const float* ar2    = (const float*)d_in[19];
    const float* b2     = (const float*)d_in[20];
    const float* w_lin2 = (const float*)d_in[21];
    const float* blast  = (const float*)d_in[22];

    __nv_bfloat16* ftb;
    float *rst, *sk;
    cudaGetSymbolAddress((void**)&ftb, g_ftb);
    cudaGetSymbolAddress((void**)&rst, g_rst);
    cudaGetSymbolAddress((void**)&sk,  g_sk);

    static cudaStream_t s2 = nullptr;
    static cudaEvent_t evF = nullptr, evJ = nullptr;
    if (!s2) {
        cudaFuncSetAttribute(scan_all_kernel,
                             cudaFuncAttributeMaxDynamicSharedMemorySize, NN * 4);
        cudaStreamCreateWithFlags(&s2, cudaStreamNonBlocking);
        cudaEventCreateWithFlags(&evF, cudaEventDisableTiming);
        cudaEventCreateWithFlags(&evJ, cudaEventDisableTiming);
    }

    const dim3 g128((NN + 255) / 256, 4);    // 256-row block tiles, fc+lin per block
    const dim3 g160((NN + 255) / 256, 5);
    const int EB   = (EE + 255) / 256;
    const int NB   = (NN + 255) / 256;
    const int NODB = (NN * 32 + 255) / 256;  // warp per node
    const int NHB  = (NN * 4 + 255) / 256;

    // ---- fork: CSR build on s2, overlapped with layer-0 GEMM ----
    cudaEventRecord(evF, 0);
    cudaStreamWaitEvent(s2, evF, 0);
    zero_all_kernel<<<NB, 256, 0, s2>>>();
    hist_kernel<<<EB, 256, 0, s2>>>(dst);
    scan_all_kernel<<<1, 1024, NN * 4, s2>>>();
    scatter_kernel<<<EB, 256, 0, s2>>>(src, dst);
    cudaEventRecord(evJ, s2);

    // ---- layer 0 (runs concurrently with CSR build) ----
    gemm_tc<128, false><<<g128, 256>>>(feat, w_fc0, w_lin0, b0, ftb, sk,
                                       al0, ar0, nullptr, nullptr, 0);
    cudaStreamWaitEvent(0, evJ, 0);          // join before message passing
    gat_node_kernel<128, 32, 0><<<NODB, 256>>>(nullptr, nullptr, 0);

    // ---- layer 1 (BN+ReLU fused into A-tile load, stats from buffer 0) ----
    gemm_tc<128, true><<<g128, 256>>>(rst, w_fc1, w_lin1, b1, ftb, sk,
                                      al1, ar1, gam0, be0, 0);
    gat_node_kernel<128, 32, 0><<<NODB, 256>>>(nullptr, nullptr, 1);

    // ---- layer 2 (BN stats from buffer 1) + fused final ----
    gemm_tc<160, true><<<g160, 256>>>(rst, w_fc2, w_lin2, b2, ftb, sk,
                                      nullptr, nullptr, gam1, be1, 1);
    elr40_kernel<<<NHB, 256>>>(al2, ar2);
    gat_node_kernel<160, 40, 1><<<NODB, 256>>>(blast, (float*)d_out, 0);
}

// round 15
// speedup vs baseline: 1.2180x; 1.2180x over previous
#include <cuda_runtime.h>
#include <cuda_bf16.h>
#include <math.h>
#include <float.h>

#define NN 50000
#define EE 800000

// ---------------- persistent scratch (device globals; no allocation) ----------------
__device__ __nv_bfloat16 g_ftb[NN * 160];   // transformed features [N, H*F], bf16
__device__ float g_rst[NN * 160];   // layer output (post message-passing)
__device__ float g_sk [NN * 160];   // skip + bias buffer
__device__ float g_el [NN * 4];
__device__ float g_er [NN * 4];
__device__ float g_ex [EE * 4];     // staging for rare high-degree nodes
__device__ int   g_rowptr[NN + 1];
__device__ int   g_tmp   [NN];
__device__ int   g_csr_src[EE];
__device__ float g_bnsum[2][128], g_bnsq[2][128];   // ping-pong BN stats

__device__ __forceinline__ float lrelu(float x) { return x > 0.f ? x : 0.2f * x; }

__device__ __forceinline__ float tf32r(float x) {
    unsigned u;
    asm("cvt.rna.tf32.f32 %0, %1;" : "=r"(u) : "f"(x));
    return __uint_as_float(u);
}

__device__ __forceinline__ void mma_tf32(float* c, const unsigned* a, const unsigned* b) {
    asm volatile(
        "mma.sync.aligned.m16n8k8.row.col.f32.tf32.tf32.f32 "
        "{%0,%1,%2,%3}, {%4,%5,%6,%7}, {%8,%9}, {%0,%1,%2,%3};\n"
        : "+f"(c[0]), "+f"(c[1]), "+f"(c[2]), "+f"(c[3])
        : "r"(a[0]), "r"(a[1]), "r"(a[2]), "r"(a[3]), "r"(b[0]), "r"(b[1]));
}

// load 4 consecutive bf16 (8 bytes) and widen to float4
__device__ __forceinline__ float4 ld_bf16x4(const __nv_bfloat16* p) {
    __nv_bfloat162 pr[2];
    *(uint2*)pr = *(const uint2*)p;
    float2 a = __bfloat1622float2(pr[0]);
    float2 b = __bfloat1622float2(pr[1]);
    return make_float4(a.x, a.y, b.x, b.y);
}

// ================= CSR build =================
__global__ void zero_all_kernel()
{
    int i = blockIdx.x * blockDim.x + threadIdx.x;
    if (i < NN)  g_tmp[i] = 0;
    if (i < 128) {
        g_bnsum[0][i] = 0.f; g_bnsq[0][i] = 0.f;
        g_bnsum[1][i] = 0.f; g_bnsq[1][i] = 0.f;
    }
}

__global__ void hist_kernel(const int* __restrict__ dst)
{
    int e = blockIdx.x * blockDim.x + threadIdx.x;
    if (e < EE) atomicAdd(&g_tmp[dst[e]], 1);
}

// one-block scan of all NN counts in dynamic smem -> g_rowptr & g_tmp
__global__ __launch_bounds__(1024) void scan_all_kernel()
{
    extern __shared__ int s_scan[];
    __shared__ int wsum[32];
    const int t = threadIdx.x, lane = t & 31, wid = t >> 5;
    for (int i = t; i < NN; i += 1024) s_scan[i] = g_tmp[i];
    __syncthreads();

    const int C = (NN + 1023) / 1024;      // 49
    const int base = t * C;
    int sum = 0;
#pragma unroll 7
    for (int i = 0; i < C; i++) {
        int idx = base + i;
        if (idx < NN) sum += s_scan[idx];
    }
    int x = sum;
#pragma unroll
    for (int o = 1; o < 32; o <<= 1) {
        int y = __shfl_up_sync(0xffffffffu, x, o);
        if (lane >= o) x += y;
    }
    if (lane == 31) wsum[wid] = x;
    __syncthreads();
    if (wid == 0) {
        int w = wsum[lane];
#pragma unroll
        for (int o = 1; o < 32; o <<= 1) {
            int y = __shfl_up_sync(0xffffffffu, w, o);
            if (lane >= o) w += y;
        }
        wsum[lane] = w;
    }
    __syncthreads();
    int run = (x - sum) + (wid ? wsum[wid - 1] : 0);
#pragma unroll 7
    for (int i = 0; i < C; i++) {
        int idx = base + i;
        if (idx < NN) { int v = s_scan[idx]; s_scan[idx] = run; run += v; }
    }
    __syncthreads();
    for (int i = t; i < NN; i += 1024) {
        int v = s_scan[i];
        g_rowptr[i] = v;
        g_tmp[i]    = v;
    }
    if (t == 0) g_rowptr[NN] = EE;
}

__global__ void scatter_kernel(const int* __restrict__ src, const int* __restrict__ dst)
{
    int e = blockIdx.x * blockDim.x + threadIdx.x;
    if (e >= EE) return;
    int pos = atomicAdd(&g_tmp[dst[e]], 1);
    g_csr_src[pos] = src[e];
}

// ---------------- merged tf32 GEMM, double-buffered + register-staged pipeline ----
// Block tile 128 rows x 32 cols per matrix; warps 0-3 -> fc, warps 4-7 -> lin.
// fc output -> bf16 g_ftb (+ optional fused el/er for OD=128); lin -> fp32 sk (+bias)
// BN: x <- relu(a*x+b) applied at the reg->smem store (overlaps mma).
#define AS_STRIDE (128 * 37)          // floats per A stage
#define BS_STRIDE (2 * 32 * 37)       // floats per B stage (both matrices)
#define SMEM_GEMM ((2 * AS_STRIDE + 2 * BS_STRIDE + 256) * 4)

template<int OD, bool BN>
__global__ __launch_bounds__(256)
void gemm_tc(const float* __restrict__ X,
             const float* __restrict__ Wfc, const float* __restrict__ Wlin,
             const float* __restrict__ bias, __nv_bfloat16* __restrict__ ft_out,
             float* __restrict__ sk_out,
             const float* __restrict__ al, const float* __restrict__ ar,
             const float* __restrict__ gam, const float* __restrict__ be, int sel)
{
    extern __shared__ float sm[];
    float* Asm = sm;                            // [2][128*37]
    float* Bsm = sm + 2 * AS_STRIDE;            // [2][2][32*37]
    float* s_a = Bsm + 2 * BS_STRIDE;
    float* s_b = s_a + 128;

    const int tid  = threadIdx.x;
    const int warp = tid >> 5, lane = tid & 31;
    const int g    = lane >> 2, t = lane & 3;
    const bool isFC = warp < 4;
    const int wr   = warp & 3;                  // 32-row group within matrix
    const int row0 = blockIdx.x * 128;
    const int cb   = blockIdx.y;
    const int col0 = cb * 32;

    if (BN) {
        if (tid < 128) {
            float sum = g_bnsum[sel][tid], sq = g_bnsq[sel][tid];
            const float invN = 1.f / (float)NN;
            float mean = sum * invN;
            float var  = sq * invN - mean * mean;
            float a = __ldg(gam + tid) * rsqrtf(var + 1e-5f);
            s_a[tid] = a;
            s_b[tid] = __ldg(be + tid) - mean * a;
        }
        __syncthreads();
    }

    // per-thread tile slots
    const int rA_r  = tid >> 3;                 // A row for this thread's slots
    const int rA_k4 = (tid & 7) << 2;           // A k-offset (float4)
    const bool rA_ok = (row0 + rA_r) < NN;
    const int rB_m  [2] = { (tid + 0) >> 8, (tid + 256) >> 8 };
    const int rB_k  [2] = { (tid & 255) >> 3, (tid & 255) >> 3 };
    const int rB_n4 [2] = { ((tid + 0) & 7) << 2, ((tid + 256) & 7) << 2 };

    float4 rA[4], rB[2];

    auto load_regs = [&](int kb) {
#pragma unroll
        for (int j = 0; j < 4; j++) {
            int r = rA_r + j * 32;              // rows rA_r, +32, +64, +96
            rA[j] = make_float4(0.f, 0.f, 0.f, 0.f);
            if (row0 + r < NN)
                rA[j] = *(const float4*)(X + (size_t)(row0 + r) * 128 + kb + rA_k4);
        }
#pragma unroll
        for (int j = 0; j < 2; j++) {
            const float* Wm = rB_m[j] ? Wlin : Wfc;
            rB[j] = *(const float4*)(Wm + (size_t)(kb + rB_k[j]) * OD + col0 + rB_n4[j]);
        }
    };
    auto store_regs = [&](int stage, int kb) {
        float* Ab = Asm + stage * AS_STRIDE;
        float* Bb = Bsm + stage * BS_STRIDE;
#pragma unroll
        for (int j = 0; j < 4; j++) {
            int r = rA_r + j * 32;
            float4 v = rA[j];
            if (BN) {
                v.x = fmaxf(s_a[kb + rA_k4 + 0] * v.x + s_b[kb + rA_k4 + 0], 0.f);
                v.y = fmaxf(s_a[kb + rA_k4 + 1] * v.y + s_b[kb + rA_k4 + 1], 0.f);
                v.z = fmaxf(s_a[kb + rA_k4 + 2] * v.z + s_b[kb + rA_k4 + 2], 0.f);
                v.w = fmaxf(s_a[kb + rA_k4 + 3] * v.w + s_b[kb + rA_k4 + 3], 0.f);
            }
            float* ap = &Ab[r * 37 + rA_k4];
            ap[0] = tf32r(v.x); ap[1] = tf32r(v.y); ap[2] = tf32r(v.z); ap[3] = tf32r(v.w);
        }
#pragma unroll
        for (int j = 0; j < 2; j++) {
            float4 v = rB[j];
            float* bp = Bb + rB_m[j] * (32 * 37);
            bp[(rB_n4[j] + 0) * 37 + rB_k[j]] = tf32r(v.x);
            bp[(rB_n4[j] + 1) * 37 + rB_k[j]] = tf32r(v.y);
            bp[(rB_n4[j] + 2) * 37 + rB_k[j]] = tf32r(v.z);
            bp[(rB_n4[j] + 3) * 37 + rB_k[j]] = tf32r(v.w);
        }
    };

    float c[2][4][4];
#pragma unroll
    for (int i = 0; i < 2; i++)
#pragma unroll
        for (int j = 0; j < 4; j++)
#pragma unroll
            for (int q = 0; q < 4; q++) c[i][j][q] = 0.f;

    // prologue: stage 0
    load_regs(0);
    store_regs(0, 0);
    __syncthreads();

#pragma unroll
    for (int s = 0; s < 4; s++) {
        const int cur = s & 1;
        if (s < 3) load_regs((s + 1) * 32);     // overlap next-tile loads with mma

        const float* Ab   = Asm + cur * AS_STRIDE;
        const float* Bsel = Bsm + cur * BS_STRIDE + (isFC ? 0 : 1) * (32 * 37);
#pragma unroll
        for (int ks = 0; ks < 4; ks++) {
            const int k0 = ks * 8;
            unsigned a[2][4], b[4][2];
            const int mbase = wr * 32;
#pragma unroll
            for (int i = 0; i < 2; i++) {
                const float* ap = Ab + (mbase + i * 16 + g) * 37 + k0 + t;
                a[i][0] = __float_as_uint(ap[0]);
                a[i][1] = __float_as_uint(ap[8 * 37]);
                a[i][2] = __float_as_uint(ap[4]);
                a[i][3] = __float_as_uint(ap[8 * 37 + 4]);
            }
#pragma unroll
            for (int j = 0; j < 4; j++) {
                const float* bp = Bsel + (j * 8 + g) * 37 + k0 + t;
                b[j][0] = __float_as_uint(bp[0]);
                b[j][1] = __float_as_uint(bp[4]);
            }
#pragma unroll
            for (int i = 0; i < 2; i++)
#pragma unroll
                for (int j = 0; j < 4; j++)
                    mma_tf32(c[i][j], a[i], b[j]);
        }
        if (s < 3) {
            store_regs(cur ^ 1, (s + 1) * 32);  // other buffer: no hazard with cur
            __syncthreads();                    // one sync per K-chunk
        }
    }

#pragma unroll
    for (int i = 0; i < 2; i++) {
        int r = row0 + wr * 32 + i * 16 + g;
#pragma unroll
        for (int j = 0; j < 4; j++) {
            int cc = col0 + j * 8 + 2 * t;
            if (isFC) {
                if (r < NN) {
                    __nv_bfloat162 o = __float22bfloat162_rn(
                        make_float2(c[i][j][0], c[i][j][1]));
                    *(__nv_bfloat162*)(ft_out + (size_t)r * OD + cc) = o;
                }
                if (r + 8 < NN) {
                    __nv_bfloat162 o = __float22bfloat162_rn(
                        make_float2(c[i][j][2], c[i][j][3]));
                    *(__nv_bfloat162*)(ft_out + (size_t)(r + 8) * OD + cc) = o;
                }
            } else {
                float bx = __ldg(bias + cc), by = __ldg(bias + cc + 1);
                if (r < NN) {
                    float2 o = make_float2(c[i][j][0] + bx, c[i][j][1] + by);
                    *(float2*)(sk_out + (size_t)r * OD + cc) = o;
                }
                if (r + 8 < NN) {
                    float2 o = make_float2(c[i][j][2] + bx, c[i][j][3] + by);
                    *(float2*)(sk_out + (size_t)(r + 8) * OD + cc) = o;
                }
            }
        }
    }

    if (OD == 128 && isFC && al != nullptr) {   // fused el/er: col block cb == head
        const int h = cb;
#pragma unroll
        for (int i = 0; i < 2; i++) {
            float el0 = 0.f, el8 = 0.f, er0 = 0.f, er8 = 0.f;
#pragma unroll
            for (int j = 0; j < 4; j++) {
                int lc = j * 8 + 2 * t;
                float a0 = __ldg(al + h * 32 + lc), a1 = __ldg(al + h * 32 + lc + 1);
                float r0 = __ldg(ar + h * 32 + lc), r1 = __ldg(ar + h * 32 + lc + 1);
                el0 += c[i][j][0] * a0 + c[i][j][1] * a1;
                el8 += c[i][j][2] * a0 + c[i][j][3] * a1;
                er0 += c[i][j][0] * r0 + c[i][j][1] * r1;
                er8 += c[i][j][2] * r0 + c[i][j][3] * r1;
            }
#pragma unroll
            for (int o = 1; o <= 2; o <<= 1) {
                el0 += __shfl_xor_sync(0xffffffffu, el0, o);
                el8 += __shfl_xor_sync(0xffffffffu, el8, o);
                er0 += __shfl_xor_sync(0xffffffffu, er0, o);
                er8 += __shfl_xor_sync(0xffffffffu, er8, o);
            }
            if (t == 0) {
                int r = row0 + wr * 32 + i * 16 + g;
                if (r < NN)     { g_el[r * 4 + h] = el0;       g_er[r * 4 + h] = er0; }
                if (r + 8 < NN) { g_el[(r + 8) * 4 + h] = el8; g_er[(r + 8) * 4 + h] = er8; }
            }
        }
    }
}

// ---------------- el/er for layer 2 (F=40, heads not block-aligned) ----------------
__global__ void elr40_kernel(const float* __restrict__ al, const float* __restrict__ ar)
{
    int i = blockIdx.x * blockDim.x + threadIdx.x;
    if (i >= NN * 4) return;
    int h = i & 3;
    const __nv_bfloat16* f = g_ftb + (size_t)(i >> 2) * 160 + h * 40;
    float a = 0.f, b = 0.f;
#pragma unroll
    for (int j = 0; j < 10; j++) {
        float4 v = ld_bf16x4(f + j * 4);
        float a0 = __ldg(al + h * 40 + j * 4 + 0), a1 = __ldg(al + h * 40 + j * 4 + 1);
        float a2 = __ldg(al + h * 40 + j * 4 + 2), a3 = __ldg(al + h * 40 + j * 4 + 3);
        float b0 = __ldg(ar + h * 40 + j * 4 + 0), b1 = __ldg(ar + h * 40 + j * 4 + 1);
        float b2 = __ldg(ar + h * 40 + j * 4 + 2), b3 = __ldg(ar + h * 40 + j * 4 + 3);
        a += v.x * a0 + v.y * a1 + v.z * a2 + v.w * a3;
        b += v.x * b0 + v.y * b1 + v.z * b2 + v.w * b3;
    }
    g_el[i] = a;
    g_er[i] = b;
}

// ================= fused per-dst softmax + aggregation (warp per node) =========
// MODE 0: rst = sk + msg, accumulate BN stats into buffer [sel].
// MODE 1: head-mean + log_softmax -> out.
template<int OD, int F, int MODE>
__global__ __launch_bounds__(256)
void gat_node_kernel(const float* __restrict__ bias_last, float* __restrict__ out, int sel)
{
    constexpr int NR = (OD / 4 + 31) / 32;
    __shared__ float s_sum[128], s_sq[128];
    __shared__ float s_row[8][160];
    __shared__ int   s_sn [8][32];
    __shared__ float s_att[8][32][4];

    const int tid = threadIdx.x;
    if (MODE == 0) {
        if (tid < 128) { s_sum[tid] = 0.f; s_sq[tid] = 0.f; }
        __syncthreads();
    }
    const int wn   = (blockIdx.x * 256 + tid) >> 5;
    const int lane = tid & 31;
    const int warp = tid >> 5;
    const bool active = wn < NN;

    float4 acc[NR];
    int headr[NR];
#pragma unroll
    for (int rp = 0; rp < NR; rp++) {
        acc[rp] = make_float4(0.f, 0.f, 0.f, 0.f);
        headr[rp] = ((lane + rp * 32) * 4) / F;
    }

    if (active) {
        const int beg = g_rowptr[wn], end = g_rowptr[wn + 1];
        const int deg = end - beg;
        const float4 er = *(const float4*)(g_er + (size_t)wn * 4);

        if (deg <= 32) {
            // ---- one gather pass, lane-local edge ----
            int sn = -1;
            float4 ev = make_float4(-FLT_MAX, -FLT_MAX, -FLT_MAX, -FLT_MAX);
            if (lane < deg) {
                sn = g_csr_src[beg + lane];
                float4 l = *(const float4*)(g_el + (size_t)sn * 4);
                ev.x = lrelu(l.x + er.x);
                ev.y = lrelu(l.y + er.y);
                ev.z = lrelu(l.z + er.z);
                ev.w = lrelu(l.w + er.w);
            }
            float4 m = ev;
#pragma unroll
            for (int o = 16; o; o >>= 1) {
                m.x = fmaxf(m.x, __shfl_xor_sync(0xffffffffu, m.x, o));
                m.y = fmaxf(m.y, __shfl_xor_sync(0xffffffffu, m.y, o));
                m.z = fmaxf(m.z, __shfl_xor_sync(0xffffffffu, m.z, o));
                m.w = fmaxf(m.w, __shfl_xor_sync(0xffffffffu, m.w, o));
            }
            float4 ex = make_float4(0.f, 0.f, 0.f, 0.f);
            if (lane < deg) {
                ex.x = __expf(ev.x - m.x);
                ex.y = __expf(ev.y - m.y);
                ex.z = __expf(ev.z - m.z);
                ex.w = __expf(ev.w - m.w);
            }
            float4 s = ex;
#pragma unroll
            for (int o = 16; o; o >>= 1) {
                s.x += __shfl_xor_sync(0xffffffffu, s.x, o);
                s.y += __shfl_xor_sync(0xffffffffu, s.y, o);
                s.z += __shfl_xor_sync(0xffffffffu, s.z, o);
                s.w += __shfl_xor_sync(0xffffffffu, s.w, o);
            }
            s_sn[warp][lane] = sn;
            s_att[warp][lane][0] = ex.x / s.x;
            s_att[warp][lane][1] = ex.y / s.y;
            s_att[warp][lane][2] = ex.z / s.z;
            s_att[warp][lane][3] = ex.w / s.w;
            __syncwarp();

            for (int i = 0; i < deg; i++) {
                int si = s_sn[warp][i];
                const __nv_bfloat16* fp = g_ftb + (size_t)si * OD;
#pragma unroll
                for (int rp = 0; rp < NR; rp++) {
                    int j4 = lane + rp * 32;
                    if (j4 < OD / 4) {
                        float a = s_att[warp][i][headr[rp]];
                        float4 f = ld_bf16x4(fp + j4 * 4);
                        acc[rp].x += a * f.x;
                        acc[rp].y += a * f.y;
                        acc[rp].z += a * f.z;
                        acc[rp].w += a * f.w;
                    }
                }
            }
        } else {
            // ---- rare high-degree fallback: 3-phase with staging ----
            float4 m = make_float4(-FLT_MAX, -FLT_MAX, -FLT_MAX, -FLT_MAX);
            for (int i = beg + lane; i < end; i += 32) {
                int sn = g_csr_src[i];
                float4 l = *(const float4*)(g_el + (size_t)sn * 4);
                m.x = fmaxf(m.x, lrelu(l.x + er.x));
                m.y = fmaxf(m.y, lrelu(l.y + er.y));
                m.z = fmaxf(m.z, lrelu(l.z + er.z));
                m.w = fmaxf(m.w, lrelu(l.w + er.w));
            }
#pragma unroll
            for (int o = 16; o; o >>= 1) {
                m.x = fmaxf(m.x, __shfl_xor_sync(0xffffffffu, m.x, o));
                m.y = fmaxf(m.y, __shfl_xor_sync(0xffffffffu, m.y, o));
                m.z = fmaxf(m.z, __shfl_xor_sync(0xffffffffu, m.z, o));
                m.w = fmaxf(m.w, __shfl_xor_sync(0xffffffffu, m.w, o));
            }
            float4 s = make_float4(0.f, 0.f, 0.f, 0.f);
            for (int i = beg + lane; i < end; i += 32) {
                int sn = g_csr_src[i];
                float4 l = *(const float4*)(g_el + (size_t)sn * 4);
                float4 ex;
                ex.x = __expf(lrelu(l.x + er.x) - m.x);
                ex.y = __expf(lrelu(l.y + er.y) - m.y);
                ex.z = __expf(lrelu(l.z + er.z) - m.z);
                ex.w = __expf(lrelu(l.w + er.w) - m.w);
                *(float4*)(g_ex + (size_t)i * 4) = ex;
                s.x += ex.x; s.y += ex.y; s.z += ex.z; s.w += ex.w;
            }
#pragma unroll
            for (int o = 16; o; o >>= 1) {
                s.x += __shfl_xor_sync(0xffffffffu, s.x, o);
                s.y += __shfl_xor_sync(0xffffffffu, s.y, o);
                s.z += __shfl_xor_sync(0xffffffffu, s.z, o);
                s.w += __shfl_xor_sync(0xffffffffu, s.w, o);
            }
            float4 inv = make_float4(1.f / s.x, 1.f / s.y, 1.f / s.z, 1.f / s.w);
            float invh[NR];
#pragma unroll
            for (int rp = 0; rp < NR; rp++) {
                int hh = headr[rp];
                invh[rp] = (hh == 0) ? inv.x : (hh == 1) ? inv.y : (hh == 2) ? inv.z : inv.w;
            }
            for (int i = beg; i < end; i++) {
                int sn = g_csr_src[i];
                float4 exv = *(const float4*)(g_ex + (size_t)i * 4);
                const __nv_bfloat16* fp = g_ftb + (size_t)sn * OD;
#pragma unroll
                for (int rp = 0; rp < NR; rp++) {
                    int j4 = lane + rp * 32;
                    if (j4 < OD / 4) {
                        int hh = headr[rp];
                        float a = ((hh == 0) ? exv.x : (hh == 1) ? exv.y :
                                   (hh == 2) ? exv.z : exv.w) * invh[rp];
                        float4 f = ld_bf16x4(fp + j4 * 4);
                        acc[rp].x += a * f.x;
                        acc[rp].y += a * f.y;
                        acc[rp].z += a * f.z;
                        acc[rp].w += a * f.w;
                    }
                }
            }
        }
    }

    if (MODE == 0) {
        if (active) {
            const float* skp = g_sk  + (size_t)wn * OD;
            float*       rp_ = g_rst + (size_t)wn * OD;
#pragma unroll
            for (int rp = 0; rp < NR; rp++) {
                int j4 = lane + rp * 32;
                if (j4 < OD / 4) {
                    float4 sk = *(const float4*)(skp + j4 * 4);
                    float4 r;
                    r.x = sk.x + acc[rp].x; r.y = sk.y + acc[rp].y;
                    r.z = sk.z + acc[rp].z; r.w = sk.w + acc[rp].w;
                    *(float4*)(rp_ + j4 * 4) = r;
                    int c0 = j4 * 4;
                    atomicAdd(&s_sum[c0 + 0], r.x); atomicAdd(&s_sq[c0 + 0], r.x * r.x);
                    atomicAdd(&s_sum[c0 + 1], r.y); atomicAdd(&s_sq[c0 + 1], r.y * r.y);
                    atomicAdd(&s_sum[c0 + 2], r.z); atomicAdd(&s_sq[c0 + 2], r.z * r.z);
                    atomicAdd(&s_sum[c0 + 3], r.w); atomicAdd(&s_sq[c0 + 3], r.w * r.w);
                }
            }
        }
        __syncthreads();
        if (tid < 128) {
            atomicAdd(&g_bnsum[sel][tid], s_sum[tid]);
            atomicAdd(&g_bnsq[sel][tid],  s_sq[tid]);
        }
    } else {
        if (active) {
            const float* skp = g_sk + (size_t)wn * OD;
#pragma unroll
            for (int rp = 0; rp < NR; rp++) {
                int j4 = lane + rp * 32;
                if (j4 < OD / 4) {
                    float4 sk = *(const float4*)(skp + j4 * 4);
                    float* d = &s_row[warp][j4 * 4];
                    d[0] = sk.x + acc[rp].x;
                    d[1] = sk.y + acc[rp].y;
                    d[2] = sk.z + acc[rp].z;
                    d[3] = sk.w + acc[rp].w;
                }
            }
            __syncwarp();
            const float* r = s_row[warp];
            float v0 = 0.25f * (r[lane] + r[40 + lane] + r[80 + lane] + r[120 + lane])
                     + __ldg(bias_last + lane);
            float v1 = -FLT_MAX;
            if (lane < 8) {
                int c1 = lane + 32;
                v1 = 0.25f * (r[c1] + r[40 + c1] + r[80 + c1] + r[120 + c1])
                   + __ldg(bias_last + c1);
            }
            float mx = fmaxf(v0, v1);
#pragma unroll
            for (int o = 16; o; o >>= 1) mx = fmaxf(mx, __shfl_xor_sync(0xffffffffu, mx, o));
            float se = __expf(v0 - mx) + (lane < 8 ? __expf(v1 - mx) : 0.f);
#pragma unroll
            for (int o = 16; o; o >>= 1) se += __shfl_xor_sync(0xffffffffu, se, o);
            float lse = logf(se);
            out[(size_t)wn * 40 + lane] = v0 - mx - lse;
            if (lane < 8) out[(size_t)wn * 40 + lane + 32] = v1 - mx - lse;
        }
    }
}

// ---------------- launch ----------------
extern "C" void kernel_launch(void* const* d_in, const int* in_sizes, int n_in,
                              void* d_out, int out_size)
{
    (void)in_sizes; (void)n_in; (void)out_size;
    const float* feat   = (const float*)d_in[0];
    const int*   src    = (const int*)  d_in[1];
    const int*   dst    = (const int*)  d_in[2];
    const float* w_fc0  = (const float*)d_in[3];
    const float* al0    = (const float*)d_in[4];
    const float* ar0    = (const float*)d_in[5];
    const float* b0     = (const float*)d_in[6];
    const float* w_lin0 = (const float*)d_in[7];
    const float* gam0   = (const float*)d_in[8];
    const float* be0    = (const float*)d_in[9];
    const float* w_fc1  = (const float*)d_in[10];
    const float* al1    = (const float*)d_in[11];
    const float* ar1    = (const float*)d_in[12];
    const float* b1     = (const float*)d_in[13];
    const float* w_lin1 = (const float*)d_in[14];
    const float* gam1   = (const float*)d_in[15];
    const float* be1    = (const float*)d_in[16];
    const float* w_fc2  = (const float*)d_in[17];
    const float* al2    = (const float*)d_in[18];
    const float* ar2    = (const float*)d_in[19];
    const float* b2     = (const float*)d_in[20];
    const float* w_lin2 = (const float*)d_in[21];
    const float* blast  = (const float*)d_in[22];

    __nv_bfloat16* ftb;
    float *rst, *sk;
    cudaGetSymbolAddress((void**)&ftb, g_ftb);
    cudaGetSymbolAddress((void**)&rst, g_rst);
    cudaGetSymbolAddress((void**)&sk,  g_sk);

    static cudaStream_t s2 = nullptr;
    static cudaEvent_t evF = nullptr, evJ = nullptr;
    if (!s2) {
        cudaFuncSetAttribute(scan_all_kernel,
                             cudaFuncAttributeMaxDynamicSharedMemorySize, NN * 4);
        cudaFuncSetAttribute(gemm_tc<128, false>,
                             cudaFuncAttributeMaxDynamicSharedMemorySize, SMEM_GEMM);
        cudaFuncSetAttribute(gemm_tc<128, true>,
                             cudaFuncAttributeMaxDynamicSharedMemorySize, SMEM_GEMM);
        cudaFuncSetAttribute(gemm_tc<160, true>,
                             cudaFuncAttributeMaxDynamicSharedMemorySize, SMEM_GEMM);
        cudaStreamCreateWithFlags(&s2, cudaStreamNonBlocking);
        cudaEventCreateWithFlags(&evF, cudaEventDisableTiming);
        cudaEventCreateWithFlags(&evJ, cudaEventDisableTiming);
    }

    const dim3 g128((NN + 127) / 128, 4);    // 128-row block tiles, fc+lin per block
    const dim3 g160((NN + 127) / 128, 5);
    const int EB   = (EE + 255) / 256;
    const int NB   = (NN + 255) / 256;
    const int NODB = (NN * 32 + 255) / 256;  // warp per node
    const int NHB  = (NN * 4 + 255) / 256;

    // ---- fork: CSR build on s2, overlapped with layer-0 GEMM ----
    cudaEventRecord(evF, 0);
    cudaStreamWaitEvent(s2, evF, 0);
    zero_all_kernel<<<NB, 256, 0, s2>>>();
    hist_kernel<<<EB, 256, 0, s2>>>(dst);
    scan_all_kernel<<<1, 1024, NN * 4, s2>>>();
    scatter_kernel<<<EB, 256, 0, s2>>>(src, dst);
    cudaEventRecord(evJ, s2);

    // ---- layer 0 (runs concurrently with CSR build) ----
    gemm_tc<128, false><<<g128, 256, SMEM_GEMM>>>(feat, w_fc0, w_lin0, b0, ftb, sk,
                                                  al0, ar0, nullptr, nullptr, 0);
    cudaStreamWaitEvent(0, evJ, 0);          // join before message passing
    gat_node_kernel<128, 32, 0><<<NODB, 256>>>(nullptr, nullptr, 0);

    // ---- layer 1 (BN+ReLU fused into A-tile load, stats from buffer 0) ----
    gemm_tc<128, true><<<g128, 256, SMEM_GEMM>>>(rst, w_fc1, w_lin1, b1, ftb, sk,
                                                 al1, ar1, gam0, be0, 0);
    gat_node_kernel<128, 32, 0><<<NODB, 256>>>(nullptr, nullptr, 1);

    // ---- layer 2 (BN stats from buffer 1) + fused final ----
    gemm_tc<160, true><<<g160, 256, SMEM_GEMM>>>(rst, w_fc2, w_lin2, b2, ftb, sk,
                                                 nullptr, nullptr, gam1, be1, 1);
    elr40_kernel<<<NHB, 256>>>(al2, ar2);
    gat_node_kernel<160, 40, 1><<<NODB, 256>>>(blast, (float*)d_out, 0);
}